// round 1
// baseline (speedup 1.0000x reference)
#include <cuda_runtime.h>
#include <math_constants.h>

#define BATCH 16
#define CH    512
#define HGT   128
#define WID   128
#define NS    8

// scratch (no allocs allowed)
__device__ int   g_rc[BATCH * HGT];   // per-(b,h) argmax-row counts (summed over c,w)
__device__ float g_F [BATCH * CH];    // per-(b,c) sum/W

__global__ void zero_rc_kernel() {
    int i = blockIdx.x * blockDim.x + threadIdx.x;
    if (i < BATCH * HGT) g_rc[i] = 0;
}

// One block per (b,c) slice of 128x128 floats (64KB).
// 256 threads = 8 warps; warp w handles rows [w*16, w*16+16).
// Per row: 32 lanes x float4 = 128 floats, perfectly coalesced.
__global__ __launch_bounds__(256) void pass1_kernel(const float* __restrict__ x) {
    const int bc   = blockIdx.x;          // 0..B*C-1
    const int b    = bc / CH;
    const int warp = threadIdx.x >> 5;
    const int lane = threadIdx.x & 31;

    const float4* base = reinterpret_cast<const float4*>(x) + (size_t)bc * (HGT * WID / 4);

    __shared__ float s_rowmax[HGT];
    __shared__ int   s_rowcnt[HGT];
    __shared__ float s_wsum[8];
    __shared__ float s_wmax[8];
    __shared__ float s_vmax;

    float wsum = 0.0f;
    float wmax = -CUDART_INF_F;

    #pragma unroll
    for (int r = 0; r < 16; r++) {
        const int row = warp * 16 + r;
        float4 v = base[row * 32 + lane];

        float m = fmaxf(fmaxf(v.x, v.y), fmaxf(v.z, v.w));
        int   c = (v.x == m) + (v.y == m) + (v.z == m) + (v.w == m);
        float s = (v.x + v.y) + (v.z + v.w);

        // warp tree-reduce: sum, and (max, tie-count) merge
        #pragma unroll
        for (int off = 16; off > 0; off >>= 1) {
            float om = __shfl_down_sync(0xffffffffu, m, off);
            int   oc = __shfl_down_sync(0xffffffffu, c, off);
            float os = __shfl_down_sync(0xffffffffu, s, off);
            s += os;
            if (om > m)       { m = om; c = oc; }
            else if (om == m) { c += oc; }
        }
        if (lane == 0) {
            s_rowmax[row] = m;
            s_rowcnt[row] = c;
            wsum += s;
            wmax = fmaxf(wmax, m);
        }
    }
    if (lane == 0) { s_wsum[warp] = wsum; s_wmax[warp] = wmax; }
    __syncthreads();

    if (threadIdx.x == 0) {
        float tot = 0.0f, vm = -CUDART_INF_F;
        #pragma unroll
        for (int w = 0; w < 8; w++) { tot += s_wsum[w]; vm = fmaxf(vm, s_wmax[w]); }
        g_F[bc] = tot * (1.0f / (float)WID);
        s_vmax = vm;
    }
    __syncthreads();

    // rows whose rowmax equals the global max contribute their tie counts
    if (threadIdx.x < HGT) {
        const int h = threadIdx.x;
        if (s_rowmax[h] == s_vmax) {
            atomicAdd(&g_rc[b * HGT + h], s_rowcnt[h]);
        }
    }
}

// One block per batch. Thread 0 reproduces the reference's SEQUENTIAL
// threshold scan exactly (only one k may fire per j), then all threads
// write the 4096 outputs.
__global__ __launch_bounds__(256) void finalize_kernel(float* __restrict__ out) {
    const int b = blockIdx.x;
    __shared__ int   s_Hc[HGT];       // exclusive cumsum
    __shared__ float s_hsub[NS];

    if (threadIdx.x == 0) {
        const int* rc = &g_rc[b * HGT];
        s_Hc[0] = 0;
        for (int i = 1; i < HGT; i++) s_Hc[i] = s_Hc[i - 1] + rc[i - 1];

        float hks[NS + 1];
        #pragma unroll
        for (int k = 0; k < NS; k++) hks[k] = 0.0f;
        hks[NS] = (float)HGT;

        int k = 1;
        for (int j = 1; j <= HGT - 2; j++) {
            const int t = (k * CH) / NS;
            if (k < NS && s_Hc[j] <= t && s_Hc[j + 1] > t) {
                hks[k] = (float)j;
                k++;
            }
        }
        #pragma unroll
        for (int kk = 0; kk < NS; kk++) s_hsub[kk] = hks[kk + 1] - hks[kk];
    }
    __syncthreads();

    const float* F = &g_F[b * CH];
    float* ob = out + (size_t)b * (NS * CH);
    for (int idx = threadIdx.x; idx < NS * CH; idx += blockDim.x) {
        const int k = idx / CH;
        const int c = idx - k * CH;
        ob[idx] = F[c] / s_hsub[k];
    }
}

extern "C" void kernel_launch(void* const* d_in, const int* in_sizes, int n_in,
                              void* d_out, int out_size) {
    const float* x = (const float*)d_in[0];
    float* out = (float*)d_out;

    zero_rc_kernel<<<(BATCH * HGT + 255) / 256, 256>>>();
    pass1_kernel<<<BATCH * CH, 256>>>(x);
    finalize_kernel<<<BATCH, 256>>>(out);
}

// round 2
// speedup vs baseline: 1.2362x; 1.2362x over previous
#include <cuda_runtime.h>
#include <math_constants.h>

#define BATCH 16
#define CH    512
#define HGT   128
#define WID   128
#define NS    8

// scratch (no allocs allowed). g_rc is zero-initialized at load; finalize
// re-zeroes it after consuming, so every launch sequence starts from zeros.
__device__ int   g_rc[BATCH * HGT];   // per-(b,h) counts of elements == slice max
__device__ float g_F [BATCH * CH];    // per-(b,c) sum/W

// One block per (b,c) slice of 128x128 floats (64KB).
// 256 threads; thread (warp,lane) holds float4 of rows warp*16+r at column lane.
// Phase A: register-resident vector max+sum, single warp reduce, block reduce.
// Phase B: re-scan registers vs vmax; rare atomic per matching element.
__global__ __launch_bounds__(256) void pass1_kernel(const float* __restrict__ x) {
    const int bc   = blockIdx.x;          // 0..B*C-1
    const int b    = bc >> 9;             // / CH
    const int warp = threadIdx.x >> 5;
    const int lane = threadIdx.x & 31;

    const float4* base = reinterpret_cast<const float4*>(x) + (size_t)bc * (HGT * WID / 4);

    // Load all 16 float4 (one per row) — independent, front-batched
    float4 v[16];
    #pragma unroll
    for (int r = 0; r < 16; r++) {
        v[r] = base[(warp * 16 + r) * 32 + lane];
    }

    // Vector sum and max trees (FMA pipe only, no shuffles)
    float4 s4 = v[0];
    float4 m4 = v[0];
    #pragma unroll
    for (int r = 1; r < 16; r++) {
        s4.x += v[r].x; s4.y += v[r].y; s4.z += v[r].z; s4.w += v[r].w;
        m4.x = fmaxf(m4.x, v[r].x); m4.y = fmaxf(m4.y, v[r].y);
        m4.z = fmaxf(m4.z, v[r].z); m4.w = fmaxf(m4.w, v[r].w);
    }
    float s = (s4.x + s4.y) + (s4.z + s4.w);
    float m = fmaxf(fmaxf(m4.x, m4.y), fmaxf(m4.z, m4.w));

    // Single warp reduce (10 shuffles total)
    #pragma unroll
    for (int off = 16; off > 0; off >>= 1) {
        s += __shfl_down_sync(0xffffffffu, s, off);
        m  = fmaxf(m, __shfl_down_sync(0xffffffffu, m, off));
    }

    __shared__ float s_wsum[8];
    __shared__ float s_wmax[8];
    __shared__ float s_vmax;
    if (lane == 0) { s_wsum[warp] = s; s_wmax[warp] = m; }
    __syncthreads();

    if (threadIdx.x == 0) {
        float tot = 0.0f, vm = -CUDART_INF_F;
        #pragma unroll
        for (int w = 0; w < 8; w++) { tot += s_wsum[w]; vm = fmaxf(vm, s_wmax[w]); }
        g_F[bc] = tot * (1.0f / (float)WID);
        s_vmax = vm;
    }
    __syncthreads();

    const float vmax = s_vmax;

    // Phase B: count elements equal to the global max, per row.
    // Typically exactly one element in the whole slice matches -> ~1 atomic/block.
    #pragma unroll
    for (int r = 0; r < 16; r++) {
        int c = (v[r].x == vmax) + (v[r].y == vmax) + (v[r].z == vmax) + (v[r].w == vmax);
        if (c) atomicAdd(&g_rc[b * HGT + warp * 16 + r], c);
    }
}

// One block per batch. 128 threads stage rc into smem (and re-zero it for the
// next replay), thread 0 reproduces the reference's SEQUENTIAL threshold scan
// exactly, then all threads write the 4096 outputs.
__global__ __launch_bounds__(256) void finalize_kernel(float* __restrict__ out) {
    const int b = blockIdx.x;
    __shared__ int   s_rc[HGT];
    __shared__ float s_hsub[NS];

    if (threadIdx.x < HGT) {
        s_rc[threadIdx.x] = g_rc[b * HGT + threadIdx.x];
        g_rc[b * HGT + threadIdx.x] = 0;      // reset for next launch/replay
    }
    __syncthreads();

    if (threadIdx.x == 0) {
        // exclusive cumsum
        int Hc[HGT];
        Hc[0] = 0;
        for (int i = 1; i < HGT; i++) Hc[i] = Hc[i - 1] + s_rc[i - 1];

        float hks[NS + 1];
        #pragma unroll
        for (int k = 0; k < NS; k++) hks[k] = 0.0f;
        hks[NS] = (float)HGT;

        int k = 1;
        for (int j = 1; j <= HGT - 2; j++) {
            const int t = (k * CH) / NS;
            if (k < NS && Hc[j] <= t && Hc[j + 1] > t) {
                hks[k] = (float)j;
                k++;
            }
        }
        #pragma unroll
        for (int kk = 0; kk < NS; kk++) s_hsub[kk] = hks[kk + 1] - hks[kk];
    }
    __syncthreads();

    const float* F = &g_F[b * CH];
    float* ob = out + (size_t)b * (NS * CH);
    for (int idx = threadIdx.x; idx < NS * CH; idx += blockDim.x) {
        const int k = idx / CH;
        const int c = idx - k * CH;
        ob[idx] = F[c] / s_hsub[k];
    }
}

extern "C" void kernel_launch(void* const* d_in, const int* in_sizes, int n_in,
                              void* d_out, int out_size) {
    const float* x = (const float*)d_in[0];
    float* out = (float*)d_out;

    pass1_kernel<<<BATCH * CH, 256>>>(x);
    finalize_kernel<<<BATCH, 256>>>(out);
}

// round 3
// speedup vs baseline: 1.3142x; 1.0631x over previous
#include <cuda_runtime.h>
#include <math_constants.h>

#define BATCH 16
#define CH    512
#define HGT   128
#define WID   128
#define NS    8

// scratch (no allocs allowed). g_rc is zero-initialized at load; finalize
// re-zeroes it after consuming, so every launch sequence starts from zeros.
__device__ int   g_rc[BATCH * HGT];   // per-(b,h) counts of elements == slice max
__device__ float g_F [BATCH * CH];    // per-(b,c) sum/W

// One block per (b,c) slice of 128x128 floats (64KB).
// 256 threads; thread (warp,lane) holds float4 of rows warp*16+r at column lane.
// Phase A: register-resident vector max+sum, single warp reduce, block reduce.
// Phase B: re-scan registers vs vmax; rare atomic per matching element.
__global__ __launch_bounds__(256) void pass1_kernel(const float* __restrict__ x) {
    const int bc   = blockIdx.x;          // 0..B*C-1
    const int b    = bc >> 9;             // / CH
    const int warp = threadIdx.x >> 5;
    const int lane = threadIdx.x & 31;

    const float4* base = reinterpret_cast<const float4*>(x) + (size_t)bc * (HGT * WID / 4);

    // Load all 16 float4 (one per row) — independent, front-batched
    float4 v[16];
    #pragma unroll
    for (int r = 0; r < 16; r++) {
        v[r] = base[(warp * 16 + r) * 32 + lane];
    }

    // Vector sum and max trees (FMA pipe only, no shuffles)
    float4 s4 = v[0];
    float4 m4 = v[0];
    #pragma unroll
    for (int r = 1; r < 16; r++) {
        s4.x += v[r].x; s4.y += v[r].y; s4.z += v[r].z; s4.w += v[r].w;
        m4.x = fmaxf(m4.x, v[r].x); m4.y = fmaxf(m4.y, v[r].y);
        m4.z = fmaxf(m4.z, v[r].z); m4.w = fmaxf(m4.w, v[r].w);
    }
    float s = (s4.x + s4.y) + (s4.z + s4.w);
    float m = fmaxf(fmaxf(m4.x, m4.y), fmaxf(m4.z, m4.w));

    // Single warp reduce (10 shuffles total)
    #pragma unroll
    for (int off = 16; off > 0; off >>= 1) {
        s += __shfl_down_sync(0xffffffffu, s, off);
        m  = fmaxf(m, __shfl_down_sync(0xffffffffu, m, off));
    }

    __shared__ float s_wsum[8];
    __shared__ float s_wmax[8];
    __shared__ float s_vmax;
    if (lane == 0) { s_wsum[warp] = s; s_wmax[warp] = m; }
    __syncthreads();

    if (threadIdx.x == 0) {
        float tot = 0.0f, vm = -CUDART_INF_F;
        #pragma unroll
        for (int w = 0; w < 8; w++) { tot += s_wsum[w]; vm = fmaxf(vm, s_wmax[w]); }
        g_F[bc] = tot * (1.0f / (float)WID);
        s_vmax = vm;
    }
    __syncthreads();

    const float vmax = s_vmax;

    // Phase B: count elements equal to the global max, per row.
    // Typically exactly one element in the whole slice matches -> ~1 atomic/block.
    #pragma unroll
    for (int r = 0; r < 16; r++) {
        int c = (v[r].x == vmax) + (v[r].y == vmax) + (v[r].z == vmax) + (v[r].w == vmax);
        if (c) atomicAdd(&g_rc[b * HGT + warp * 16 + r], c);
    }
}

// One block per batch. 128 threads stage rc into smem (and re-zero it for the
// next replay). Thread 0 builds the exclusive cumsum IN SHARED MEMORY (no
// local-array spill) and runs the reference-exact sequential threshold scan;
// then all threads write the 4096 outputs.
__global__ __launch_bounds__(256) void finalize_kernel(float* __restrict__ out) {
    const int b = blockIdx.x;
    __shared__ int   s_rc[HGT];
    __shared__ int   s_Hc[HGT];       // exclusive cumsum, in smem (no spills)
    __shared__ float s_hsub[NS];

    if (threadIdx.x < HGT) {
        s_rc[threadIdx.x] = g_rc[b * HGT + threadIdx.x];
        g_rc[b * HGT + threadIdx.x] = 0;      // reset for next launch/replay
    }
    __syncthreads();

    if (threadIdx.x == 0) {
        // exclusive cumsum: 4-cyc ALU chain; LDS feeds pipeline under unroll
        int acc = 0;
        s_Hc[0] = 0;
        #pragma unroll
        for (int i = 1; i < HGT; i++) {
            acc += s_rc[i - 1];
            s_Hc[i] = acc;
        }

        float hks[NS + 1];
        #pragma unroll
        for (int k = 0; k < NS; k++) hks[k] = 0.0f;
        hks[NS] = (float)HGT;

        // reference-exact sequential scan; loads are scan-state-independent
        int k = 1;
        #pragma unroll
        for (int j = 1; j <= HGT - 2; j++) {
            const int hj  = s_Hc[j];
            const int hj1 = s_Hc[j + 1];
            const int t   = k * (CH / NS);          // k*512/8 = k*64
            if (k < NS && hj <= t && hj1 > t) {
                hks[k] = (float)j;
                k++;
            }
        }
        #pragma unroll
        for (int kk = 0; kk < NS; kk++) s_hsub[kk] = hks[kk + 1] - hks[kk];
    }
    __syncthreads();

    const float* F = &g_F[b * CH];
    float* ob = out + (size_t)b * (NS * CH);
    for (int idx = threadIdx.x; idx < NS * CH; idx += blockDim.x) {
        const int k = idx / CH;
        const int c = idx - k * CH;
        ob[idx] = F[c] / s_hsub[k];
    }
}

extern "C" void kernel_launch(void* const* d_in, const int* in_sizes, int n_in,
                              void* d_out, int out_size) {
    const float* x = (const float*)d_in[0];
    float* out = (float*)d_out;

    pass1_kernel<<<BATCH * CH, 256>>>(x);
    finalize_kernel<<<BATCH, 256>>>(out);
}